// round 1
// baseline (speedup 1.0000x reference)
#include <cuda_runtime.h>
#include <math.h>

// ---------------- problem constants ----------------
#define NTOK   6272          // B*N = 32*196 tokens
#define DMODEL 768
#define FFDIM  3072
#define QKVDIM 2304
#define NHEAD  12
#define DHEAD  64
#define NSEQ   196
#define NLAYER 12

// ---------------- scratch (device globals; no allocation allowed) ----------------
__device__ float g_h  [NTOK * DMODEL];   // residual stream
__device__ float g_y  [NTOK * DMODEL];   // LN output
__device__ float g_qkv[NTOK * QKVDIM];
__device__ float g_o  [NTOK * DMODEL];   // attention output
__device__ float g_ff [NTOK * FFDIM];
__device__ float g_im [NTOK * DMODEL];   // im2col patches

// ---------------- im2col: (B,3,224,224) -> (6272, 768) with (c,i,j) inner order ----------------
__global__ void im2col_kernel(const float* __restrict__ x, float* __restrict__ out) {
    int idx = blockIdx.x * 256 + threadIdx.x;
    if (idx >= NTOK * DMODEL) return;
    int t = idx / 768, r = idx % 768;
    int c = r >> 8;               // /256
    int ij = r & 255;
    int i = ij >> 4, j = ij & 15;
    int b = t / 196, p = t % 196;
    int py = p / 14, px = p % 14;
    out[idx] = x[((size_t)(b * 3 + c) * 224 + py * 16 + i) * 224 + px * 16 + j];
}

// ---------------- GEMM: C[M,N] = A[M,K] @ W[N,K]^T + bias (+gelu) (+pos) (+res) ----------------
// 128x128 block tile, BK=16, 256 threads, 8x8 per thread.
// All M,N divisible by 128; all K divisible by 16 in this model -> no bounds checks.
__global__ void __launch_bounds__(256) gemm_kernel(
    const float* __restrict__ A, const float* __restrict__ W,
    const float* __restrict__ bias, const float* __restrict__ res,
    const float* __restrict__ pos, float* __restrict__ C,
    int M, int N, int K, int act)
{
    __shared__ float As[16][128];
    __shared__ float Ws[16][128];
    const int tid = threadIdx.x;
    const int bm = blockIdx.y * 128;
    const int bn = blockIdx.x * 128;
    const int tx = tid & 15;        // n dim
    const int ty = tid >> 4;        // m dim
    const int lrow = tid >> 2;      // 0..63 (loader row)
    const int lcol = (tid & 3) << 2;// 0,4,8,12 (loader k)

    float acc[8][8];
#pragma unroll
    for (int i = 0; i < 8; i++)
#pragma unroll
        for (int j = 0; j < 8; j++) acc[i][j] = 0.f;

    const float* Ap0 = A + (size_t)(bm + lrow)      * K + lcol;
    const float* Ap1 = A + (size_t)(bm + lrow + 64) * K + lcol;
    const float* Wp0 = W + (size_t)(bn + lrow)      * K + lcol;
    const float* Wp1 = W + (size_t)(bn + lrow + 64) * K + lcol;

    for (int k0 = 0; k0 < K; k0 += 16) {
        float4 a0 = *(const float4*)(Ap0 + k0);
        float4 a1 = *(const float4*)(Ap1 + k0);
        float4 w0 = *(const float4*)(Wp0 + k0);
        float4 w1 = *(const float4*)(Wp1 + k0);
        __syncthreads();   // previous iteration's reads done
        As[lcol + 0][lrow] = a0.x; As[lcol + 1][lrow] = a0.y;
        As[lcol + 2][lrow] = a0.z; As[lcol + 3][lrow] = a0.w;
        As[lcol + 0][lrow + 64] = a1.x; As[lcol + 1][lrow + 64] = a1.y;
        As[lcol + 2][lrow + 64] = a1.z; As[lcol + 3][lrow + 64] = a1.w;
        Ws[lcol + 0][lrow] = w0.x; Ws[lcol + 1][lrow] = w0.y;
        Ws[lcol + 2][lrow] = w0.z; Ws[lcol + 3][lrow] = w0.w;
        Ws[lcol + 0][lrow + 64] = w1.x; Ws[lcol + 1][lrow + 64] = w1.y;
        Ws[lcol + 2][lrow + 64] = w1.z; Ws[lcol + 3][lrow + 64] = w1.w;
        __syncthreads();
#pragma unroll
        for (int k = 0; k < 16; k++) {
            float ra[8], rb[8];
            *(float4*)&ra[0] = *(const float4*)&As[k][ty * 4];
            *(float4*)&ra[4] = *(const float4*)&As[k][64 + ty * 4];
            *(float4*)&rb[0] = *(const float4*)&Ws[k][tx * 4];
            *(float4*)&rb[4] = *(const float4*)&Ws[k][64 + tx * 4];
#pragma unroll
            for (int i = 0; i < 8; i++)
#pragma unroll
                for (int j = 0; j < 8; j++)
                    acc[i][j] += ra[i] * rb[j];
        }
    }

#pragma unroll
    for (int i = 0; i < 8; i++) {
        int m = bm + (i < 4 ? ty * 4 + i : 64 + ty * 4 + (i - 4));
        const float* resrow = res ? res + (size_t)m * N : nullptr;
        const float* posrow = pos ? pos + (size_t)(m % 196) * N : nullptr;
        float* crow = C + (size_t)m * N;
#pragma unroll
        for (int j = 0; j < 8; j++) {
            int n = bn + (j < 4 ? tx * 4 + j : 64 + tx * 4 + (j - 4));
            float v = acc[i][j] + bias[n];
            if (act) v = 0.5f * v * (1.f + erff(v * 0.70710678118654752f));
            if (posrow) v += posrow[n];
            if (resrow) v += resrow[n];
            crow[n] = v;
        }
    }
}

// ---------------- LayerNorm: per token, D=768, 256 threads/block ----------------
__global__ void __launch_bounds__(256) ln_kernel(
    const float* __restrict__ X, const float* __restrict__ w,
    const float* __restrict__ b, float* __restrict__ Y)
{
    const int t = blockIdx.x;
    const int tid = threadIdx.x;
    const float* xr = X + (size_t)t * DMODEL;
    float v0 = xr[tid], v1 = xr[tid + 256], v2 = xr[tid + 512];
    float s  = v0 + v1 + v2;
    float s2 = v0 * v0 + v1 * v1 + v2 * v2;
#pragma unroll
    for (int o = 16; o > 0; o >>= 1) {
        s  += __shfl_xor_sync(0xffffffffu, s,  o);
        s2 += __shfl_xor_sync(0xffffffffu, s2, o);
    }
    __shared__ float rs[8], rs2[8];
    __shared__ float mS, rS;
    int wid = tid >> 5, lane = tid & 31;
    if (lane == 0) { rs[wid] = s; rs2[wid] = s2; }
    __syncthreads();
    if (tid == 0) {
        float S = 0.f, S2 = 0.f;
        for (int k = 0; k < 8; k++) { S += rs[k]; S2 += rs2[k]; }
        float m = S * (1.f / 768.f);
        float var = S2 * (1.f / 768.f) - m * m;
        mS = m;
        rS = rsqrtf(var + 1e-5f);
    }
    __syncthreads();
    float m = mS, r = rS;
    float* yr = Y + (size_t)t * DMODEL;
    yr[tid]       = (v0 - m) * r * w[tid]       + b[tid];
    yr[tid + 256] = (v1 - m) * r * w[tid + 256] + b[tid + 256];
    yr[tid + 512] = (v2 - m) * r * w[tid + 512] + b[tid + 512];
}

// ---------------- Fused attention: one CTA per (b,h); K/V/Q/S resident in SMEM ----------------
#define NP 208   // keys padded to 13*16
#define ATTN_SMEM_FLOATS (64 * NP + NP * 64 + 64 * 64 + 64 * NP)
#define ATTN_SMEM_BYTES  (ATTN_SMEM_FLOATS * 4)

__global__ void __launch_bounds__(256) attn_kernel(
    const float* __restrict__ qkv, float* __restrict__ O)
{
    extern __shared__ float sm[];
    float* Kt = sm;                    // [64][NP]   K transposed (d-major), pad cols zero
    float* Vs = Kt + 64 * NP;          // [NP][64]   V, pad rows zero
    float* Qt = Vs + NP * 64;          // [64][64]   Q tile transposed (d-major), pre-scaled
    float* Ss = Qt + 64 * 64;          // [64][NP]   scores / probs

    const int tid = threadIdx.x;
    const int b = blockIdx.x / NHEAD;
    const int h = blockIdx.x % NHEAD;
    const float scale = 0.125f;        // 1/sqrt(64)
    const size_t base = (size_t)b * NSEQ * QKVDIM + h * DHEAD;

    // load K,V (zero padding rows/cols)
    for (int idx = tid; idx < NP * 64; idx += 256) {
        int m = idx >> 6, d = idx & 63;
        float kv = 0.f, vv = 0.f;
        if (m < NSEQ) {
            kv = qkv[base + (size_t)m * QKVDIM + 768  + d];
            vv = qkv[base + (size_t)m * QKVDIM + 1536 + d];
        }
        Kt[d * NP + m] = kv;
        Vs[m * 64 + d] = vv;
    }
    __syncthreads();

    const int tx = tid & 15, ty = tid >> 4;
    const int wid = tid >> 5, lane = tid & 31;

    for (int q0 = 0; q0 < NSEQ; q0 += 64) {
        // load Q tile transposed, pre-scaled (clamp padded rows; their output is never written)
        for (int idx = tid; idx < 64 * 64; idx += 256) {
            int i = idx >> 6, d = idx & 63;
            int r = q0 + i; if (r > NSEQ - 1) r = NSEQ - 1;
            Qt[d * 64 + i] = qkv[base + (size_t)r * QKVDIM + d] * scale;
        }
        __syncthreads();

        // S[64][208] = Q @ K^T ; thread tile 4(rows) x 13(strided cols)
        float acc[4][13];
#pragma unroll
        for (int i = 0; i < 4; i++)
#pragma unroll
            for (int j = 0; j < 13; j++) acc[i][j] = 0.f;
        for (int d = 0; d < 64; d++) {
            float ra[4];
            *(float4*)ra = *(const float4*)&Qt[d * 64 + ty * 4];
            float rb[13];
#pragma unroll
            for (int j = 0; j < 13; j++) rb[j] = Kt[d * NP + tx + j * 16];
#pragma unroll
            for (int i = 0; i < 4; i++)
#pragma unroll
                for (int j = 0; j < 13; j++) acc[i][j] += ra[i] * rb[j];
        }
#pragma unroll
        for (int i = 0; i < 4; i++)
#pragma unroll
            for (int j = 0; j < 13; j++)
                Ss[(ty * 4 + i) * NP + tx + j * 16] = acc[i][j];
        __syncthreads();

        // softmax over the 196 real keys; zero the 12 pad columns
        for (int row = wid; row < 64; row += 8) {
            float* srow = Ss + row * NP;
            float mx = -1e30f;
            for (int m = lane; m < NSEQ; m += 32) mx = fmaxf(mx, srow[m]);
#pragma unroll
            for (int o = 16; o > 0; o >>= 1) mx = fmaxf(mx, __shfl_xor_sync(0xffffffffu, mx, o));
            float sum = 0.f;
            for (int m = lane; m < NSEQ; m += 32) {
                float e = expf(srow[m] - mx);
                srow[m] = e;
                sum += e;
            }
#pragma unroll
            for (int o = 16; o > 0; o >>= 1) sum += __shfl_xor_sync(0xffffffffu, sum, o);
            float inv = 1.f / sum;
            for (int m = lane; m < NSEQ; m += 32) srow[m] *= inv;
            if (lane < NP - NSEQ) srow[NSEQ + lane] = 0.f;
        }
        __syncthreads();

        // O tile [64][64] = P @ V ; thread tile 4x4 (strided cols)
        float acc2[4][4];
#pragma unroll
        for (int i = 0; i < 4; i++)
#pragma unroll
            for (int j = 0; j < 4; j++) acc2[i][j] = 0.f;
        for (int m = 0; m < NP; m++) {
            float rb2[4];
#pragma unroll
            for (int j = 0; j < 4; j++) rb2[j] = Vs[m * 64 + tx + j * 16];
#pragma unroll
            for (int i = 0; i < 4; i++) {
                float pa = Ss[(ty * 4 + i) * NP + m];
#pragma unroll
                for (int j = 0; j < 4; j++) acc2[i][j] += pa * rb2[j];
            }
        }
#pragma unroll
        for (int i = 0; i < 4; i++) {
            int r = q0 + ty * 4 + i;
            if (r < NSEQ) {
#pragma unroll
                for (int j = 0; j < 4; j++)
                    O[(size_t)(b * NSEQ + r) * DMODEL + h * DHEAD + tx + j * 16] = acc2[i][j];
            }
        }
        __syncthreads();  // before Qt/Ss reuse in next tile
    }
}

// ---------------- launch ----------------
extern "C" void kernel_launch(void* const* d_in, const int* in_sizes, int n_in,
                              void* d_out, int out_size)
{
    const float* x       = (const float*)d_in[0];
    const float* patch_w = (const float*)d_in[1];
    const float* patch_b = (const float*)d_in[2];
    const float* pos     = (const float*)d_in[3];
    const float* ln1_w   = (const float*)d_in[4];
    const float* ln1_b   = (const float*)d_in[5];
    const float* qkv_w   = (const float*)d_in[6];
    const float* qkv_b   = (const float*)d_in[7];
    const float* proj_w  = (const float*)d_in[8];
    const float* proj_b  = (const float*)d_in[9];
    const float* ln2_w   = (const float*)d_in[10];
    const float* ln2_b   = (const float*)d_in[11];
    const float* fc1_w   = (const float*)d_in[12];
    const float* fc1_b   = (const float*)d_in[13];
    const float* fc2_w   = (const float*)d_in[14];
    const float* fc2_b   = (const float*)d_in[15];
    const float* lnf_w   = (const float*)d_in[16];
    const float* lnf_b   = (const float*)d_in[17];

    float *h, *y, *qkv, *o, *ff, *im;
    cudaGetSymbolAddress((void**)&h,   g_h);
    cudaGetSymbolAddress((void**)&y,   g_y);
    cudaGetSymbolAddress((void**)&qkv, g_qkv);
    cudaGetSymbolAddress((void**)&o,   g_o);
    cudaGetSymbolAddress((void**)&ff,  g_ff);
    cudaGetSymbolAddress((void**)&im,  g_im);

    cudaFuncSetAttribute(attn_kernel, cudaFuncAttributeMaxDynamicSharedMemorySize, ATTN_SMEM_BYTES);

    // patch embed: im2col + GEMM (bias + pos-embed fused in epilogue)
    im2col_kernel<<<(NTOK * DMODEL + 255) / 256, 256>>>(x, im);
    gemm_kernel<<<dim3(DMODEL / 128, NTOK / 128), 256>>>(
        im, patch_w, patch_b, nullptr, pos, h, NTOK, DMODEL, DMODEL, 0);

    for (int l = 0; l < NLAYER; l++) {
        ln_kernel<<<NTOK, 256>>>(h, ln1_w + l * DMODEL, ln1_b + l * DMODEL, y);
        gemm_kernel<<<dim3(QKVDIM / 128, NTOK / 128), 256>>>(
            y, qkv_w + (size_t)l * QKVDIM * DMODEL, qkv_b + l * QKVDIM,
            nullptr, nullptr, qkv, NTOK, QKVDIM, DMODEL, 0);
        attn_kernel<<<32 * NHEAD, 256, ATTN_SMEM_BYTES>>>(qkv, o);
        gemm_kernel<<<dim3(DMODEL / 128, NTOK / 128), 256>>>(
            o, proj_w + (size_t)l * DMODEL * DMODEL, proj_b + l * DMODEL,
            h, nullptr, h, NTOK, DMODEL, DMODEL, 0);
        ln_kernel<<<NTOK, 256>>>(h, ln2_w + l * DMODEL, ln2_b + l * DMODEL, y);
        gemm_kernel<<<dim3(FFDIM / 128, NTOK / 128), 256>>>(
            y, fc1_w + (size_t)l * FFDIM * DMODEL, fc1_b + l * FFDIM,
            nullptr, nullptr, ff, NTOK, FFDIM, DMODEL, 1);
        gemm_kernel<<<dim3(DMODEL / 128, NTOK / 128), 256>>>(
            ff, fc2_w + (size_t)l * DMODEL * FFDIM, fc2_b + l * DMODEL,
            h, nullptr, h, NTOK, DMODEL, FFDIM, 0);
    }
    ln_kernel<<<NTOK, 256>>>(h, lnf_w, lnf_b, (float*)d_out);
}